// round 5
// baseline (speedup 1.0000x reference)
#include <cuda_runtime.h>
#include <math.h>

typedef unsigned long long u64;

#define PI2_128 0.04908738521234052f   // 2*pi/128

__device__ __forceinline__ u64 pk2(float lo, float hi) {
    u64 r; asm("mov.b64 %0,{%1,%2};" : "=l"(r) : "f"(lo), "f"(hi)); return r;
}
__device__ __forceinline__ void upk2(u64 a, float& lo, float& hi) {
    asm("mov.b64 {%0,%1},%2;" : "=f"(lo), "=f"(hi) : "l"(a));
}
__device__ __forceinline__ u64 f2fma(u64 a, u64 b, u64 c) {
    u64 d; asm("fma.rn.f32x2 %0,%1,%2,%3;" : "=l"(d) : "l"(a), "l"(b), "l"(c)); return d;
}
__device__ __forceinline__ float shrinkf(float v) {
    float a = fabsf(v) - 0.01f;
    return a > 0.f ? copysignf(a, v) : 0.f;
}

// Scratch: 3600 rows (b*450+m) x 768 channels, complex (re,im).
__device__ float2 g_X[3600 * 768];
__device__ float2 g_F[3600 * 768];

// ===========================================================================
// Kernel 1: forward pruned DFT + freq-embed.  One CTA per (b,c).
// smem: twW u64[15*128] | G2 u64[128*16] | ccT u64[128] | ssT u64[128] |
//       img f32[128*132] | cosB f32[128] | sinB f32[128]   = 112,400 B
// ===========================================================================
#define K1_SMEM 112400

__global__ __launch_bounds__(256) void k_fwd(const float* __restrict__ x,
                                             const float* __restrict__ alpha)
{
    extern __shared__ u64 smu[];
    u64* twW = smu;                      // 1920
    u64* G2  = twW + 1920;               // 2048
    u64* ccT = G2 + 2048;                // 128
    u64* ssT = ccT + 128;                // 128
    float* img  = (float*)(ssT + 128);   // 128*132 (16B aligned: offset 43792)
    float* cosB = img + 128 * 132;       // 128
    float* sinB = cosB + 128;            // 128

    const int t  = threadIdx.x;
    const int bc = blockIdx.x;
    const int b  = bc / 768, c = bc - b * 768;

    // phase A: base trig + image load
    if (t < 128) {
        float cv, sv;
        sincosf(t * PI2_128, &sv, &cv);
        cosB[t] = cv; sinB[t] = sv;
        ccT[t] = pk2(cv, cv);
        ssT[t] = pk2(sv, sv);
    }
    {
        const float4* src = (const float4*)(x + (size_t)bc * 16384);
        for (int i = t; i < 4096; i += 256) {
            float4 v = src[i];
            int y = i >> 5, xx = (i & 31) << 2;
            float* d = img + y * 132 + xx;
            d[0] = v.x; d[1] = v.y; d[2] = v.z; d[3] = v.w;
        }
    }
    __syncthreads();

    // phase B: per-w twiddle (cos, -sin) for w = wi+2
    for (int i = t; i < 1920; i += 256) {
        int wi = i >> 7, xx = i & 127;
        int a = ((wi + 2) * xx) & 127;
        twW[i] = pk2(cosB[a], -sinB[a]);
    }
    __syncthreads();

    // stage 1: G[y][w] = sum_x img[y][x] * e^{-i w x a}
    {
        const int wi = t & 15;            // 15 active, lane 15 idle
        const int yg = t >> 4;            // 0..15, rows yg*8 .. +7
        u64 acc[8];
        #pragma unroll
        for (int j = 0; j < 8; j++) acc[j] = 0ull;
        const u64* twrow = twW + ((wi < 15) ? wi : 0) * 128;
        const float* imgb = img + (yg * 8) * 132;
        for (int xb = 0; xb < 32; xb++) {
            u64 tw0 = twrow[xb*4+0], tw1 = twrow[xb*4+1];
            u64 tw2 = twrow[xb*4+2], tw3 = twrow[xb*4+3];
            #pragma unroll
            for (int j = 0; j < 8; j++) {
                float4 v = *(const float4*)(imgb + j * 132 + xb * 4);
                acc[j] = f2fma(pk2(v.x, v.x), tw0, acc[j]);
                acc[j] = f2fma(pk2(v.y, v.y), tw1, acc[j]);
                acc[j] = f2fma(pk2(v.z, v.z), tw2, acc[j]);
                acc[j] = f2fma(pk2(v.w, v.w), tw3, acc[j]);
            }
        }
        if (wi < 15) {
            #pragma unroll
            for (int j = 0; j < 8; j++) G2[(yg * 8 + j) * 16 + wi] = acc[j];
        }
    }
    __syncthreads();

    // stage 2: X[h] = (C - iS)/128, X[128-h] = (C + iS)/128, + alpha*FREQ_EMB
    if (t < 225) {
        const int wi = t % 15, hIdx = t / 15;
        const int h = hIdx + 2;
        u64 C = 0ull, S = 0ull;
        int idx = 0;
        #pragma unroll 4
        for (int y = 0; y < 128; y++) {
            u64 g = G2[y * 16 + wi];
            C = f2fma(g, ccT[idx], C);
            S = f2fma(g, ssT[idx], S);
            idx = (idx + h) & 127;
        }
        float Cr, Ci, Sr, Si;
        upk2(C, Cr, Ci); upk2(S, Sr, Si);
        const float sc = 1.0f / 128.0f;
        float X1r = (Cr + Si) * sc, X1i = (Ci - Sr) * sc;
        float X2r = (Cr - Si) * sc, X2i = (Ci + Sr) * sc;

        // freq embed: c<384 uses position h (and 128-h), c>=384 uses w
        float al = alpha[c];
        int cb = (c < 384) ? c : (c - 384);
        float dv = expf((float)(cb & ~1) * (-9.210340371976184f / 384.0f));
        float p1, p2;
        if (c < 384) { p1 = (float)h; p2 = (float)(128 - h); }
        else         { p1 = p2 = (float)(wi + 2); }
        float e1, e2;
        if (c & 1) { e1 = cosf(p1 * dv); e2 = cosf(p2 * dv); }
        else       { e1 = sinf(p1 * dv); e2 = sinf(p2 * dv); }
        X1r += al * e1; X2r += al * e2;

        int m1 = hIdx * 15 + wi;            // h = hIdx+2
        int m2 = (29 - hIdx) * 15 + wi;     // h' = 128-h
        size_t base = ((size_t)b * 450) * 768 + c;
        g_X[base + (size_t)m1 * 768] = make_float2(X1r, X1i);
        g_X[base + (size_t)m2 * 768] = make_float2(X2r, X2i);
    }
}

// ===========================================================================
// Kernel 2: complex MLP per block k (96->96->96) + soft shrink.
// grid (113, 8); CTA handles 32 rows. smem = 198,656 B.
// ===========================================================================
#define K2_SMEM 198656

__global__ __launch_bounds__(256) void k_mlp(
    const float* __restrict__ w1r, const float* __restrict__ b1r,
    const float* __restrict__ w1i, const float* __restrict__ b1i,
    const float* __restrict__ w2r, const float* __restrict__ b2r,
    const float* __restrict__ w2i, const float* __restrict__ b2i)
{
    extern __shared__ u64 smu[];
    u64* Xt  = smu;                      // 32*97
    u64* Mid = Xt + 32 * 97;             // 32*97
    float* sW1r = (float*)(Mid + 32 * 97);
    float* sW1i = sW1r + 9216;
    float* sW2r = sW1i + 9216;
    float* sW2i = sW2r + 9216;
    float* sb   = sW2i + 9216;           // b1r|b1i|b2r|b2i, 96 each

    const int t  = threadIdx.x;
    const int k  = blockIdx.y;
    const int r0 = blockIdx.x * 32;
    const int wo = k * 9216;

    for (int i = t; i < 9216; i += 256) {
        sW1r[i] = w1r[wo + i];
        sW1i[i] = w1i[wo + i];
        sW2r[i] = w2r[wo + i];
        sW2i[i] = w2i[wo + i];
    }
    if (t < 96) {
        sb[t]       = b1r[k * 96 + t];
        sb[96 + t]  = b1i[k * 96 + t];
        sb[192 + t] = b2r[k * 96 + t];
        sb[288 + t] = b2i[k * 96 + t];
    }
    for (int i = t; i < 32 * 96; i += 256) {
        int r = i / 96, ci = i - r * 96;
        int R = r0 + r; if (R > 3599) R = 3599;
        Xt[r * 97 + ci] = *(const u64*)&g_X[(size_t)R * 768 + k * 96 + ci];
    }
    __syncthreads();

    const int r  = t & 31;               // lane = row
    const int cg = t >> 5;               // warp = 12-col group
    const int c0 = cg * 12;
    u64 ar[6], ai[6];

    // ---- layer 1 ----
    #pragma unroll
    for (int p = 0; p < 6; p++) {
        int cc = c0 + 2 * p;
        float br0 = sb[cc], bi0 = sb[96 + cc];
        float br1 = sb[cc + 1], bi1 = sb[96 + cc + 1];
        ar[p] = pk2(br0 - bi0, br1 - bi1);
        ai[p] = pk2(br0 + bi0, br1 + bi1);
    }
    {
        const u64* xrow = Xt + r * 97;
        #pragma unroll 4
        for (int i = 0; i < 96; i++) {
            float xr, xi; upk2(xrow[i], xr, xi);
            u64 xrr = pk2(xr, xr), xii = pk2(xi, xi), xin = pk2(-xi, -xi);
            const float* wr  = sW1r + i * 96 + c0;
            const float* wii = sW1i + i * 96 + c0;
            #pragma unroll
            for (int p = 0; p < 6; p++) {
                u64 wr2 = *(const u64*)(wr + 2 * p);
                u64 wi2 = *(const u64*)(wii + 2 * p);
                ar[p] = f2fma(xrr, wr2, ar[p]);
                ar[p] = f2fma(xin, wi2, ar[p]);
                ai[p] = f2fma(xii, wr2, ai[p]);
                ai[p] = f2fma(xrr, wi2, ai[p]);
            }
        }
    }
    #pragma unroll
    for (int p = 0; p < 6; p++) {
        float r1a, r1b, i1a, i1b;
        upk2(ar[p], r1a, r1b); upk2(ai[p], i1a, i1b);
        Mid[r * 97 + c0 + 2 * p]     = pk2(r1a, i1a);
        Mid[r * 97 + c0 + 2 * p + 1] = pk2(r1b, i1b);
    }
    __syncthreads();

    // ---- layer 2 ----
    #pragma unroll
    for (int p = 0; p < 6; p++) {
        int cc = c0 + 2 * p;
        float br0 = sb[192 + cc], bi0 = sb[288 + cc];
        float br1 = sb[192 + cc + 1], bi1 = sb[288 + cc + 1];
        ar[p] = pk2(br0 - bi0, br1 - bi1);
        ai[p] = pk2(br0 + bi0, br1 + bi1);
    }
    {
        const u64* mrow = Mid + r * 97;
        #pragma unroll 4
        for (int i = 0; i < 96; i++) {
            float xr, xi; upk2(mrow[i], xr, xi);
            u64 xrr = pk2(xr, xr), xii = pk2(xi, xi), xin = pk2(-xi, -xi);
            const float* wr  = sW2r + i * 96 + c0;
            const float* wii = sW2i + i * 96 + c0;
            #pragma unroll
            for (int p = 0; p < 6; p++) {
                u64 wr2 = *(const u64*)(wr + 2 * p);
                u64 wi2 = *(const u64*)(wii + 2 * p);
                ar[p] = f2fma(xrr, wr2, ar[p]);
                ar[p] = f2fma(xin, wi2, ar[p]);
                ai[p] = f2fma(xii, wr2, ai[p]);
                ai[p] = f2fma(xrr, wi2, ai[p]);
            }
        }
    }
    int R = r0 + r;
    if (R < 3600) {
        float2* dst = g_F + (size_t)R * 768 + k * 96 + c0;
        #pragma unroll
        for (int p = 0; p < 6; p++) {
            float ra, rb, ia, ib;
            upk2(ar[p], ra, rb); upk2(ai[p], ia, ib);
            dst[2 * p]     = make_float2(shrinkf(ra), shrinkf(ia));
            dst[2 * p + 1] = make_float2(shrinkf(rb), shrinkf(ib));
        }
    }
}

// ===========================================================================
// Kernel 3: sparse inverse DFT.  One CTA per (b,c).
// smem: Fp u64[900] | csT/scT/ccT/snT u64[128]x4 | P u64[30*128] |
//       Ua f32[1920] | Ub f32[1920]   = 57,376 B
// ===========================================================================
#define K3_SMEM 57376

__global__ __launch_bounds__(256, 2) void k_inv(float* __restrict__ out)
{
    extern __shared__ u64 smu[];
    u64* Fp  = smu;                  // [ (hi*15+w)*2 + {0: (Fr,Fr), 1: (Fi,Fi)} ]
    u64* csT = Fp + 900;             // (cos, sin)
    u64* scT = csT + 128;            // (-sin, cos)
    u64* ccT = scT + 128;            // (cos, cos)
    u64* snT = ccT + 128;            // (-sin, -sin)
    u64* P   = snT + 128;            // [hi*128 + x] = (Pr, Pi)
    float* Ua = (float*)(P + 30 * 128);  // [hp*128 + x]
    float* Ub = Ua + 1920;

    const int t  = threadIdx.x;
    const int bc = blockIdx.x;
    const int b  = bc / 768, c = bc - b * 768;

    if (t < 128) {
        float cv, sv;
        sincosf(t * PI2_128, &sv, &cv);
        csT[t] = pk2(cv, sv);
        scT[t] = pk2(-sv, cv);
        ccT[t] = pk2(cv, cv);
        snT[t] = pk2(-sv, -sv);
    }
    for (int i = t; i < 450; i += 256) {
        float2 f = g_F[((size_t)b * 450 + i) * 768 + c];
        Fp[2 * i]     = pk2(f.x, f.x);
        Fp[2 * i + 1] = pk2(f.y, f.y);
    }
    __syncthreads();

    // stage 1: P[hi][x] = sum_w F[hi][w] e^{+i (w+2) x a}
    if (t < 240) {
        const int hi = t % 30, xg = t / 30;
        u64 Fr2[15], Fi2[15];
        #pragma unroll
        for (int w = 0; w < 15; w++) {
            Fr2[w] = Fp[(hi * 15 + w) * 2];
            Fi2[w] = Fp[(hi * 15 + w) * 2 + 1];
        }
        for (int xx = xg * 16; xx < xg * 16 + 16; xx++) {
            u64 acc = 0ull;
            int idx = (2 * xx) & 127;
            #pragma unroll
            for (int w = 0; w < 15; w++) {
                acc = f2fma(Fr2[w], csT[idx], acc);
                acc = f2fma(Fi2[w], scT[idx], acc);
                idx = (idx + xx) & 127;
            }
            P[hi * 128 + xx] = acc;
        }
    }
    __syncthreads();

    // fold Hermitian h-pairs: h = hp+2 with partner 128-h (hi2 = 29-hp)
    for (int i = t; i < 1920; i += 256) {
        int hp = i >> 7, xx = i & 127;
        float pr1, pi1, pr2, pi2;
        upk2(P[hp * 128 + xx], pr1, pi1);
        upk2(P[(29 - hp) * 128 + xx], pr2, pi2);
        Ua[i] = pr1 + pr2;
        Ub[i] = pi1 - pi2;
    }
    __syncthreads();

    // stage 2: out[y][x] = (1/64) sum_hp [ Ua cos(h y a) - Ub sin(h y a) ]
    {
        const int xg = t & 7, yg = t >> 3;   // 8 x-groups x 32 y-groups
        const int x0 = xg * 16;
        const int y0 = yg * 4;
        u64 acc[4][8];
        #pragma unroll
        for (int jy = 0; jy < 4; jy++)
            #pragma unroll
            for (int p = 0; p < 8; p++) acc[jy][p] = 0ull;

        for (int hp = 0; hp < 15; hp++) {
            u64 ua[8], ub[8];
            const float* uap = Ua + hp * 128 + x0;
            const float* ubp = Ub + hp * 128 + x0;
            #pragma unroll
            for (int p = 0; p < 8; p++) {
                ua[p] = *(const u64*)(uap + 2 * p);
                ub[p] = *(const u64*)(ubp + 2 * p);
            }
            const int h = hp + 2;
            #pragma unroll
            for (int jy = 0; jy < 4; jy++) {
                int idx = (h * (y0 + jy)) & 127;
                u64 cc = ccT[idx], sn = snT[idx];
                #pragma unroll
                for (int p = 0; p < 8; p++) {
                    acc[jy][p] = f2fma(ua[p], cc, acc[jy][p]);
                    acc[jy][p] = f2fma(ub[p], sn, acc[jy][p]);
                }
            }
        }
        float* outp = out + (size_t)bc * 16384;
        const float s = 1.0f / 64.0f;
        #pragma unroll
        for (int jy = 0; jy < 4; jy++) {
            float tmp[16];
            #pragma unroll
            for (int p = 0; p < 8; p++) {
                float a, bv; upk2(acc[jy][p], a, bv);
                tmp[2 * p] = a * s; tmp[2 * p + 1] = bv * s;
            }
            float* row = outp + (y0 + jy) * 128 + x0;
            #pragma unroll
            for (int q = 0; q < 4; q++)
                ((float4*)row)[q] = make_float4(tmp[4*q], tmp[4*q+1], tmp[4*q+2], tmp[4*q+3]);
        }
    }
}

// ===========================================================================
extern "C" void kernel_launch(void* const* d_in, const int* in_sizes, int n_in,
                              void* d_out, int out_size)
{
    const float* x     = (const float*)d_in[0];
    const float* alpha = (const float*)d_in[1];
    const float* w1r   = (const float*)d_in[2];
    const float* b1r   = (const float*)d_in[3];
    const float* w1i   = (const float*)d_in[4];
    const float* b1i   = (const float*)d_in[5];
    const float* w2r   = (const float*)d_in[6];
    const float* b2r   = (const float*)d_in[7];
    const float* w2i   = (const float*)d_in[8];
    const float* b2i   = (const float*)d_in[9];
    float* out = (float*)d_out;

    cudaFuncSetAttribute(k_fwd, cudaFuncAttributeMaxDynamicSharedMemorySize, K1_SMEM);
    cudaFuncSetAttribute(k_mlp, cudaFuncAttributeMaxDynamicSharedMemorySize, K2_SMEM);
    cudaFuncSetAttribute(k_inv, cudaFuncAttributeMaxDynamicSharedMemorySize, K3_SMEM);

    k_fwd<<<6144, 256, K1_SMEM>>>(x, alpha);
    k_mlp<<<dim3(113, 8), 256, K2_SMEM>>>(w1r, b1r, w1i, b1i, w2r, b2r, w2i, b2i);
    k_inv<<<6144, 256, K3_SMEM>>>(out);
}

// round 6
// speedup vs baseline: 1.6957x; 1.6957x over previous
#include <cuda_runtime.h>
#include <math.h>

typedef unsigned long long u64;

#define PI2_128 0.04908738521234052f   // 2*pi/128

__device__ __forceinline__ u64 pk2(float lo, float hi) {
    u64 r; asm("mov.b64 %0,{%1,%2};" : "=l"(r) : "f"(lo), "f"(hi)); return r;
}
__device__ __forceinline__ void upk2(u64 a, float& lo, float& hi) {
    asm("mov.b64 {%0,%1},%2;" : "=f"(lo), "=f"(hi) : "l"(a));
}
__device__ __forceinline__ u64 f2fma(u64 a, u64 b, u64 c) {
    u64 d; asm("fma.rn.f32x2 %0,%1,%2,%3;" : "=l"(d) : "l"(a), "l"(b), "l"(c)); return d;
}
__device__ __forceinline__ u64 f2add(u64 a, u64 b) {
    u64 d; asm("add.rn.f32x2 %0,%1,%2;" : "=l"(d) : "l"(a), "l"(b)); return d;
}
__device__ __forceinline__ float shrinkf(float v) {
    float a = fabsf(v) - 0.01f;
    return a > 0.f ? copysignf(a, v) : 0.f;
}

// Scratch: 3600 rows (b*450+m) x 768 channels, complex (re,im).
__device__ float2 g_X[3600 * 768];
__device__ float2 g_F[3600 * 768];

// ===========================================================================
// Kernel 1: forward pruned DFT + freq-embed.  One CTA per (b,c).
// smem: twW u64[128*16] ([x][wi], conflict-free) | G2 u64[128*17] (padded) |
//       ccT u64[128] | ssT u64[128] | img f32[128*132] | cosB/sinB f32[128]
//   = (2048+2176+256)*8 + 128*132*4 + 1024 = 104,448 B  -> 2 CTAs/SM
// ===========================================================================
#define K1_SMEM 104448

__global__ __launch_bounds__(256, 2) void k_fwd(const float* __restrict__ x,
                                                const float* __restrict__ alpha)
{
    extern __shared__ u64 smu[];
    u64* twW = smu;                      // 2048: [xx*16 + wi]
    u64* G2  = twW + 2048;               // 2176: [y*17 + wi]
    u64* ccT = G2 + 2176;                // 128
    u64* ssT = ccT + 128;                // 128
    float* img  = (float*)(ssT + 128);   // 128*132 (16B-aligned)
    float* cosB = img + 128 * 132;       // 128
    float* sinB = cosB + 128;            // 128

    const int t  = threadIdx.x;
    const int bc = blockIdx.x;
    const int b  = bc / 768, c = bc - b * 768;

    // phase A: base trig + image load
    if (t < 128) {
        float cv, sv;
        sincosf(t * PI2_128, &sv, &cv);
        cosB[t] = cv; sinB[t] = sv;
        ccT[t] = pk2(cv, cv);
        ssT[t] = pk2(sv, sv);
    }
    {
        const float4* src = (const float4*)(x + (size_t)bc * 16384);
        for (int i = t; i < 4096; i += 256) {
            float4 v = src[i];
            int y = i >> 5, xx = (i & 31) << 2;
            float* d = img + y * 132 + xx;
            d[0] = v.x; d[1] = v.y; d[2] = v.z; d[3] = v.w;
        }
    }
    __syncthreads();

    // phase B: per-w twiddle (cos, -sin), transposed layout [x][wi]
    for (int i = t; i < 2048; i += 256) {
        int xx = i >> 4, wi = i & 15;
        if (wi < 15) {
            int a = ((wi + 2) * xx) & 127;
            twW[i] = pk2(cosB[a], -sinB[a]);
        } else {
            twW[i] = 0ull;
        }
    }
    __syncthreads();

    // stage 1: G[y][w] = sum_x img[y][x] * e^{-i w x a}
    {
        const int wi = t & 15;            // lane 15 computes garbage (zeros), not stored
        const int yg = t >> 4;            // 0..15, rows yg*8 .. +7
        u64 acc[8];
        #pragma unroll
        for (int j = 0; j < 8; j++) acc[j] = 0ull;
        const float* imgb = img + (yg * 8) * 132;
        for (int xb = 0; xb < 32; xb++) {
            u64 tw0 = twW[(xb * 4 + 0) * 16 + wi];
            u64 tw1 = twW[(xb * 4 + 1) * 16 + wi];
            u64 tw2 = twW[(xb * 4 + 2) * 16 + wi];
            u64 tw3 = twW[(xb * 4 + 3) * 16 + wi];
            #pragma unroll
            for (int j = 0; j < 8; j++) {
                float4 v = *(const float4*)(imgb + j * 132 + xb * 4);
                acc[j] = f2fma(pk2(v.x, v.x), tw0, acc[j]);
                acc[j] = f2fma(pk2(v.y, v.y), tw1, acc[j]);
                acc[j] = f2fma(pk2(v.z, v.z), tw2, acc[j]);
                acc[j] = f2fma(pk2(v.w, v.w), tw3, acc[j]);
            }
        }
        if (wi < 15) {
            #pragma unroll
            for (int j = 0; j < 8; j++) G2[(yg * 8 + j) * 17 + wi] = acc[j];
        }
    }
    __syncthreads();

    // stage 2: X[h] = (C - iS)/128, X[128-h] = (C + iS)/128, + alpha*FREQ_EMB
    if (t < 225) {
        const int wi = t % 15, hIdx = t / 15;
        const int h = hIdx + 2;
        u64 C0 = 0ull, S0 = 0ull, C1 = 0ull, S1 = 0ull;
        const int step = (2 * h) & 127;
        int iA = 0, iB = h;
        #pragma unroll 4
        for (int u = 0; u < 64; u++) {
            u64 gA = G2[(2 * u) * 17 + wi];
            u64 gB = G2[(2 * u + 1) * 17 + wi];
            C0 = f2fma(gA, ccT[iA], C0);
            S0 = f2fma(gA, ssT[iA], S0);
            C1 = f2fma(gB, ccT[iB], C1);
            S1 = f2fma(gB, ssT[iB], S1);
            iA = (iA + step) & 127;
            iB = (iB + step) & 127;
        }
        u64 C = f2add(C0, C1), S = f2add(S0, S1);
        float Cr, Ci, Sr, Si;
        upk2(C, Cr, Ci); upk2(S, Sr, Si);
        const float sc = 1.0f / 128.0f;
        float X1r = (Cr + Si) * sc, X1i = (Ci - Sr) * sc;
        float X2r = (Cr - Si) * sc, X2i = (Ci + Sr) * sc;

        // freq embed: c<384 uses position h (and 128-h), c>=384 uses w
        float al = alpha[c];
        int cb = (c < 384) ? c : (c - 384);
        float dv = expf((float)(cb & ~1) * (-9.210340371976184f / 384.0f));
        float p1, p2;
        if (c < 384) { p1 = (float)h; p2 = (float)(128 - h); }
        else         { p1 = p2 = (float)(wi + 2); }
        float e1, e2;
        if (c & 1) { e1 = cosf(p1 * dv); e2 = cosf(p2 * dv); }
        else       { e1 = sinf(p1 * dv); e2 = sinf(p2 * dv); }
        X1r += al * e1; X2r += al * e2;

        int m1 = hIdx * 15 + wi;            // h = hIdx+2
        int m2 = (29 - hIdx) * 15 + wi;     // h' = 128-h
        size_t base = ((size_t)b * 450) * 768 + c;
        g_X[base + (size_t)m1 * 768] = make_float2(X1r, X1i);
        g_X[base + (size_t)m2 * 768] = make_float2(X2r, X2i);
    }
}

// ===========================================================================
// Kernel 2: complex MLP per block k (96->96->96) + soft shrink.
// grid (113, 8); CTA handles 32 rows. smem = 198,656 B.
// ===========================================================================
#define K2_SMEM 198656

__global__ __launch_bounds__(256) void k_mlp(
    const float* __restrict__ w1r, const float* __restrict__ b1r,
    const float* __restrict__ w1i, const float* __restrict__ b1i,
    const float* __restrict__ w2r, const float* __restrict__ b2r,
    const float* __restrict__ w2i, const float* __restrict__ b2i)
{
    extern __shared__ u64 smu[];
    u64* Xt  = smu;                      // 32*97
    u64* Mid = Xt + 32 * 97;             // 32*97
    float* sW1r = (float*)(Mid + 32 * 97);
    float* sW1i = sW1r + 9216;
    float* sW2r = sW1i + 9216;
    float* sW2i = sW2r + 9216;
    float* sb   = sW2i + 9216;           // b1r|b1i|b2r|b2i, 96 each

    const int t  = threadIdx.x;
    const int k  = blockIdx.y;
    const int r0 = blockIdx.x * 32;
    const int wo = k * 9216;

    for (int i = t; i < 9216; i += 256) {
        sW1r[i] = w1r[wo + i];
        sW1i[i] = w1i[wo + i];
        sW2r[i] = w2r[wo + i];
        sW2i[i] = w2i[wo + i];
    }
    if (t < 96) {
        sb[t]       = b1r[k * 96 + t];
        sb[96 + t]  = b1i[k * 96 + t];
        sb[192 + t] = b2r[k * 96 + t];
        sb[288 + t] = b2i[k * 96 + t];
    }
    for (int i = t; i < 32 * 96; i += 256) {
        int r = i / 96, ci = i - r * 96;
        int R = r0 + r; if (R > 3599) R = 3599;
        Xt[r * 97 + ci] = *(const u64*)&g_X[(size_t)R * 768 + k * 96 + ci];
    }
    __syncthreads();

    const int r  = t & 31;               // lane = row
    const int cg = t >> 5;               // warp = 12-col group
    const int c0 = cg * 12;
    u64 ar[6], ai[6];

    // ---- layer 1 ----
    #pragma unroll
    for (int p = 0; p < 6; p++) {
        int cc = c0 + 2 * p;
        float br0 = sb[cc], bi0 = sb[96 + cc];
        float br1 = sb[cc + 1], bi1 = sb[96 + cc + 1];
        ar[p] = pk2(br0 - bi0, br1 - bi1);
        ai[p] = pk2(br0 + bi0, br1 + bi1);
    }
    {
        const u64* xrow = Xt + r * 97;
        #pragma unroll 4
        for (int i = 0; i < 96; i++) {
            float xr, xi; upk2(xrow[i], xr, xi);
            u64 xrr = pk2(xr, xr), xii = pk2(xi, xi), xin = pk2(-xi, -xi);
            const float* wr  = sW1r + i * 96 + c0;
            const float* wii = sW1i + i * 96 + c0;
            #pragma unroll
            for (int p = 0; p < 6; p++) {
                u64 wr2 = *(const u64*)(wr + 2 * p);
                u64 wi2 = *(const u64*)(wii + 2 * p);
                ar[p] = f2fma(xrr, wr2, ar[p]);
                ar[p] = f2fma(xin, wi2, ar[p]);
                ai[p] = f2fma(xii, wr2, ai[p]);
                ai[p] = f2fma(xrr, wi2, ai[p]);
            }
        }
    }
    #pragma unroll
    for (int p = 0; p < 6; p++) {
        float r1a, r1b, i1a, i1b;
        upk2(ar[p], r1a, r1b); upk2(ai[p], i1a, i1b);
        Mid[r * 97 + c0 + 2 * p]     = pk2(r1a, i1a);
        Mid[r * 97 + c0 + 2 * p + 1] = pk2(r1b, i1b);
    }
    __syncthreads();

    // ---- layer 2 ----
    #pragma unroll
    for (int p = 0; p < 6; p++) {
        int cc = c0 + 2 * p;
        float br0 = sb[192 + cc], bi0 = sb[288 + cc];
        float br1 = sb[192 + cc + 1], bi1 = sb[288 + cc + 1];
        ar[p] = pk2(br0 - bi0, br1 - bi1);
        ai[p] = pk2(br0 + bi0, br1 + bi1);
    }
    {
        const u64* mrow = Mid + r * 97;
        #pragma unroll 4
        for (int i = 0; i < 96; i++) {
            float xr, xi; upk2(mrow[i], xr, xi);
            u64 xrr = pk2(xr, xr), xii = pk2(xi, xi), xin = pk2(-xi, -xi);
            const float* wr  = sW2r + i * 96 + c0;
            const float* wii = sW2i + i * 96 + c0;
            #pragma unroll
            for (int p = 0; p < 6; p++) {
                u64 wr2 = *(const u64*)(wr + 2 * p);
                u64 wi2 = *(const u64*)(wii + 2 * p);
                ar[p] = f2fma(xrr, wr2, ar[p]);
                ar[p] = f2fma(xin, wi2, ar[p]);
                ai[p] = f2fma(xii, wr2, ai[p]);
                ai[p] = f2fma(xrr, wi2, ai[p]);
            }
        }
    }
    int R = r0 + r;
    if (R < 3600) {
        float2* dst = g_F + (size_t)R * 768 + k * 96 + c0;
        #pragma unroll
        for (int p = 0; p < 6; p++) {
            float ra, rb, ia, ib;
            upk2(ar[p], ra, rb); upk2(ai[p], ia, ib);
            dst[2 * p]     = make_float2(shrinkf(ra), shrinkf(ia));
            dst[2 * p + 1] = make_float2(shrinkf(rb), shrinkf(ib));
        }
    }
}

// ===========================================================================
// Kernel 3: sparse inverse DFT.  One CTA per (b,c).
// smem: Fp u64[900] | csT/scT/ccT/snT u64[128]x4 | P u64[30*128] |
//       Ua f32[1920] | Ub f32[1920]   = 57,376 B
// ===========================================================================
#define K3_SMEM 57376

__global__ __launch_bounds__(256, 2) void k_inv(float* __restrict__ out)
{
    extern __shared__ u64 smu[];
    u64* Fp  = smu;                  // [ (hi*15+w)*2 + {0: (Fr,Fr), 1: (Fi,Fi)} ]
    u64* csT = Fp + 900;             // (cos, sin)
    u64* scT = csT + 128;            // (-sin, cos)
    u64* ccT = scT + 128;            // (cos, cos)
    u64* snT = ccT + 128;            // (-sin, -sin)
    u64* P   = snT + 128;            // [hi*128 + x] = (Pr, Pi)
    float* Ua = (float*)(P + 30 * 128);  // [hp*128 + x]
    float* Ub = Ua + 1920;

    const int t  = threadIdx.x;
    const int bc = blockIdx.x;
    const int b  = bc / 768, c = bc - b * 768;

    if (t < 128) {
        float cv, sv;
        sincosf(t * PI2_128, &sv, &cv);
        csT[t] = pk2(cv, sv);
        scT[t] = pk2(-sv, cv);
        ccT[t] = pk2(cv, cv);
        snT[t] = pk2(-sv, -sv);
    }
    for (int i = t; i < 450; i += 256) {
        float2 f = g_F[((size_t)b * 450 + i) * 768 + c];
        Fp[2 * i]     = pk2(f.x, f.x);
        Fp[2 * i + 1] = pk2(f.y, f.y);
    }
    __syncthreads();

    // stage 1: P[hi][x] = sum_w F[hi][w] e^{+i (w+2) x a}
    if (t < 240) {
        const int hi = t % 30, xg = t / 30;
        u64 Fr2[15], Fi2[15];
        #pragma unroll
        for (int w = 0; w < 15; w++) {
            Fr2[w] = Fp[(hi * 15 + w) * 2];
            Fi2[w] = Fp[(hi * 15 + w) * 2 + 1];
        }
        for (int xx = xg * 16; xx < xg * 16 + 16; xx++) {
            const int stp = (2 * xx) & 127;
            u64 aA = 0ull, aB = 0ull;
            int iA = stp;                 // w=0  -> (2)*xx
            int iB = (3 * xx) & 127;      // w=1  -> (3)*xx
            #pragma unroll
            for (int w = 0; w < 15; w += 2) {
                aA = f2fma(Fr2[w], csT[iA], aA);
                aA = f2fma(Fi2[w], scT[iA], aA);
                iA = (iA + stp) & 127;
            }
            #pragma unroll
            for (int w = 1; w < 15; w += 2) {
                aB = f2fma(Fr2[w], csT[iB], aB);
                aB = f2fma(Fi2[w], scT[iB], aB);
                iB = (iB + stp) & 127;
            }
            P[hi * 128 + xx] = f2add(aA, aB);
        }
    }
    __syncthreads();

    // fold Hermitian h-pairs: h = hp+2 with partner 128-h (hi2 = 29-hp)
    for (int i = t; i < 1920; i += 256) {
        int hp = i >> 7, xx = i & 127;
        float pr1, pi1, pr2, pi2;
        upk2(P[hp * 128 + xx], pr1, pi1);
        upk2(P[(29 - hp) * 128 + xx], pr2, pi2);
        Ua[i] = pr1 + pr2;
        Ub[i] = pi1 - pi2;
    }
    __syncthreads();

    // stage 2: out[y][x] = (1/64) sum_hp [ Ua cos(h y a) - Ub sin(h y a) ]
    // x-tiling interleaved: thread (xg) owns x-pairs {2*xg + 16*p}, p=0..7
    // -> Ua/Ub u64 loads hit 8 distinct bank-pairs (conflict-free).
    {
        const int xg = t & 7, yg = t >> 3;   // 8 x-groups x 32 y-groups
        const int y0 = yg * 4;
        u64 acc[4][8];
        #pragma unroll
        for (int jy = 0; jy < 4; jy++)
            #pragma unroll
            for (int p = 0; p < 8; p++) acc[jy][p] = 0ull;

        for (int hp = 0; hp < 15; hp++) {
            u64 ua[8], ub[8];
            const float* uap = Ua + hp * 128 + 2 * xg;
            const float* ubp = Ub + hp * 128 + 2 * xg;
            #pragma unroll
            for (int p = 0; p < 8; p++) {
                ua[p] = *(const u64*)(uap + 16 * p);
                ub[p] = *(const u64*)(ubp + 16 * p);
            }
            const int h = hp + 2;
            #pragma unroll
            for (int jy = 0; jy < 4; jy++) {
                int idx = (h * (y0 + jy)) & 127;
                u64 cc = ccT[idx], sn = snT[idx];
                #pragma unroll
                for (int p = 0; p < 8; p++) {
                    acc[jy][p] = f2fma(ua[p], cc, acc[jy][p]);
                    acc[jy][p] = f2fma(ub[p], sn, acc[jy][p]);
                }
            }
        }
        float* outp = out + (size_t)bc * 16384 + 2 * xg;
        const float s = 1.0f / 64.0f;
        #pragma unroll
        for (int jy = 0; jy < 4; jy++) {
            float* row = outp + (y0 + jy) * 128;
            #pragma unroll
            for (int p = 0; p < 8; p++) {
                float a, bv; upk2(acc[jy][p], a, bv);
                *(float2*)(row + 16 * p) = make_float2(a * s, bv * s);
            }
        }
    }
}

// ===========================================================================
extern "C" void kernel_launch(void* const* d_in, const int* in_sizes, int n_in,
                              void* d_out, int out_size)
{
    const float* x     = (const float*)d_in[0];
    const float* alpha = (const float*)d_in[1];
    const float* w1r   = (const float*)d_in[2];
    const float* b1r   = (const float*)d_in[3];
    const float* w1i   = (const float*)d_in[4];
    const float* b1i   = (const float*)d_in[5];
    const float* w2r   = (const float*)d_in[6];
    const float* b2r   = (const float*)d_in[7];
    const float* w2i   = (const float*)d_in[8];
    const float* b2i   = (const float*)d_in[9];
    float* out = (float*)d_out;

    cudaFuncSetAttribute(k_fwd, cudaFuncAttributeMaxDynamicSharedMemorySize, K1_SMEM);
    cudaFuncSetAttribute(k_mlp, cudaFuncAttributeMaxDynamicSharedMemorySize, K2_SMEM);
    cudaFuncSetAttribute(k_inv, cudaFuncAttributeMaxDynamicSharedMemorySize, K3_SMEM);

    k_fwd<<<6144, 256, K1_SMEM>>>(x, alpha);
    k_mlp<<<dim3(113, 8), 256, K2_SMEM>>>(w1r, b1r, w1i, b1i, w2r, b2r, w2i, b2i);
    k_inv<<<6144, 256, K3_SMEM>>>(out);
}

// round 8
// speedup vs baseline: 2.0685x; 1.2199x over previous
#include <cuda_runtime.h>
#include <math.h>

typedef unsigned long long u64;

#define PI2_128 0.04908738521234052f   // 2*pi/128

__device__ __forceinline__ u64 pk2(float lo, float hi) {
    u64 r; asm("mov.b64 %0,{%1,%2};" : "=l"(r) : "f"(lo), "f"(hi)); return r;
}
__device__ __forceinline__ void upk2(u64 a, float& lo, float& hi) {
    asm("mov.b64 {%0,%1},%2;" : "=f"(lo), "=f"(hi) : "l"(a));
}
__device__ __forceinline__ u64 f2fma(u64 a, u64 b, u64 c) {
    u64 d; asm("fma.rn.f32x2 %0,%1,%2,%3;" : "=l"(d) : "l"(a), "l"(b), "l"(c)); return d;
}
__device__ __forceinline__ u64 f2add(u64 a, u64 b) {
    u64 d; asm("add.rn.f32x2 %0,%1,%2;" : "=l"(d) : "l"(a), "l"(b)); return d;
}
__device__ __forceinline__ float shrinkf(float v) {
    float a = fabsf(v) - 0.01f;
    return a > 0.f ? copysignf(a, v) : 0.f;
}

// Scratch: 3600 rows (b*450+m) x 768 channels, complex (re,im).
__device__ float2 g_X[3600 * 768];
__device__ float2 g_F[3600 * 768];

// ===========================================================================
// Kernel 1: forward pruned DFT with x- and y-folding.  One CTA per (b,c).
// smem layout (u64 units):
//   EO  [0     .. 8448)   128 y * 66 x-slots, (E,O) pairs
//   tw  [8448  .. 9504)   66 x * 16 wi, (cos, -sin)
//   G2  [9504  .. 11552)  128 y * 16 wi, (Gre, Gim)
//   Gpm [11552 .. 13600)  64 y * 16 wi * ulonglong2 (Gp, Gm)
//   cs4 [13600 .. 13856)  128 * ulonglong2 ((c,c),(s,s))
//   cosB/sinB [13856 .. 13984)  f32[128] each
// total 13984*8 = 111,872 B  -> 2 CTAs/SM
// ===========================================================================
#define K1_SMEM 111872

__global__ __launch_bounds__(256, 2) void k_fwd(const float* __restrict__ x,
                                                const float* __restrict__ alpha)
{
    extern __shared__ u64 smu[];
    u64* EO  = smu;                       // [y*66 + x]
    u64* tw  = smu + 8448;                // [x*16 + wi]
    u64* G2  = smu + 9504;                // [y*16 + wi]
    ulonglong2* Gpm = (ulonglong2*)(smu + 11552);  // [y*16 + wi]
    ulonglong2* cs4 = (ulonglong2*)(smu + 13600);  // [idx]
    float* cosB = (float*)(smu + 13856);  // 128
    float* sinB = cosB + 128;             // 128

    const int t  = threadIdx.x;
    const int bc = blockIdx.x;
    const int b  = bc / 768, c = bc - b * 768;

    // ---- trig tables ----
    if (t < 128) {
        float cv, sv;
        sincosf(t * PI2_128, &sv, &cv);
        cosB[t] = cv; sinB[t] = sv;
        ulonglong2 e; e.x = pk2(cv, cv); e.y = pk2(sv, sv);
        cs4[t] = e;
    }

    // ---- fold pass: gmem -> EO (x-symmetry), coalesced + warp shuffles ----
    {
        const int wrp = t >> 5, l = t & 31;
        const float* src = x + (size_t)bc * 16384;
        for (int i = 0; i < 16; i++) {
            int y = wrp * 16 + i;
            const float* row = src + y * 128;
            float a = row[l], cc_ = row[32 + l], d = row[64 + l], bb_ = row[96 + l];
            float bsh = __shfl_sync(0xffffffffu, bb_, (32 - l) & 31);  // v[128-l] (l>=1)
            float dsh = __shfl_sync(0xffffffffu, d,   (32 - l) & 31);  // v[96-l]  (l>=1)
            float b0  = __shfl_sync(0xffffffffu, bb_, 0);              // v[96]
            float E0, O0, E1, O1;
            if (l == 0) { E0 = a; O0 = 0.f; E1 = cc_ + b0; O1 = cc_ - b0; }
            else        { E0 = a + bsh; O0 = a - bsh; E1 = cc_ + dsh; O1 = cc_ - dsh; }
            EO[y * 66 + l]      = pk2(E0, O0);
            EO[y * 66 + 32 + l] = pk2(E1, O1);
            if (l == 0) EO[y * 66 + 64] = pk2(d, 0.f);   // v[64]
            if (l == 1) EO[y * 66 + 65] = 0ull;          // pad
        }
    }
    __syncthreads();

    // ---- tw table: (cos, -sin) for x=0..64, wi=0..14 (wi 15 & x 65 = 0) ----
    for (int i = t; i < 66 * 16; i += 256) {
        int xx = i >> 4, wi = i & 15;
        if (wi < 15 && xx <= 64) {
            int a = ((wi + 2) * xx) & 127;
            tw[i] = pk2(cosB[a], -sinB[a]);
        } else {
            tw[i] = 0ull;
        }
    }
    __syncthreads();

    // ---- stage 1: G[y][w] = (Sum E cos, -Sum O sin) over x=0..64 ----
    {
        const int wq = t & 7;          // 2 wi per thread: 2wq, 2wq+1
        const int yg = t >> 3;         // 4 y per thread
        u64 acc[4][2];
        #pragma unroll
        for (int jy = 0; jy < 4; jy++) { acc[jy][0] = 0ull; acc[jy][1] = 0ull; }
        const int wi0 = wq * 2;
        for (int s = 0; s < 33; s++) {         // x = 2s, 2s+1
            u64 t00 = tw[(2 * s) * 16 + wi0];
            u64 t01 = tw[(2 * s) * 16 + wi0 + 1];
            u64 t10 = tw[(2 * s + 1) * 16 + wi0];
            u64 t11 = tw[(2 * s + 1) * 16 + wi0 + 1];
            #pragma unroll
            for (int jy = 0; jy < 4; jy++) {
                ulonglong2 eo = *(const ulonglong2*)(EO + (yg * 4 + jy) * 66 + 2 * s);
                acc[jy][0] = f2fma(eo.x, t00, acc[jy][0]);
                acc[jy][1] = f2fma(eo.x, t01, acc[jy][1]);
                acc[jy][0] = f2fma(eo.y, t10, acc[jy][0]);
                acc[jy][1] = f2fma(eo.y, t11, acc[jy][1]);
            }
        }
        #pragma unroll
        for (int jy = 0; jy < 4; jy++) {
            G2[(yg * 4 + jy) * 16 + wi0]     = acc[jy][0];
            G2[(yg * 4 + jy) * 16 + wi0 + 1] = acc[jy][1];
        }
    }
    __syncthreads();

    // ---- G fold over y: Gpm[y][wi] = (G[y]+G[128-y], G[y]-G[128-y]) ----
    for (int idx = t; idx < 64 * 16; idx += 256) {
        int y = idx >> 4, wi = idx & 15;
        ulonglong2 e;
        if (y == 0) { e.x = G2[wi]; e.y = 0ull; }
        else {
            u64 a = G2[y * 16 + wi], bq = G2[(128 - y) * 16 + wi];
            float ar, ai, br2, bi2;
            upk2(a, ar, ai); upk2(bq, br2, bi2);
            e.x = pk2(ar + br2, ai + bi2);
            e.y = pk2(ar - br2, ai - bi2);
        }
        Gpm[idx] = e;
    }
    __syncthreads();

    // ---- stage 2 (folded y): C = Sum Gp cos(hy), S = Sum Gm sin(hy) ----
    if (t < 225) {
        const int wi = t % 15, hIdx = t / 15;
        const int h = hIdx + 2;
        u64 C0 = 0ull, S0 = 0ull, C1 = 0ull, S1 = 0ull;
        const int step = (2 * h) & 127;
        int iA = 0, iB = h;
        #pragma unroll 4
        for (int u = 0; u < 32; u++) {
            ulonglong2 gA = Gpm[(2 * u) * 16 + wi];
            ulonglong2 gB = Gpm[(2 * u + 1) * 16 + wi];
            ulonglong2 tA = cs4[iA];
            ulonglong2 tB = cs4[iB];
            C0 = f2fma(gA.x, tA.x, C0);
            S0 = f2fma(gA.y, tA.y, S0);
            C1 = f2fma(gB.x, tB.x, C1);
            S1 = f2fma(gB.y, tB.y, S1);
            iA = (iA + step) & 127;
            iB = (iB + step) & 127;
        }
        // y = 64 term: + G[64] * cos(64 h theta) = +- G[64]
        {
            u64 g64 = G2[64 * 16 + wi];
            float sg = (hIdx & 1) ? -1.0f : 1.0f;
            C0 = f2fma(g64, pk2(sg, sg), C0);
        }
        u64 C = f2add(C0, C1), S = f2add(S0, S1);
        float Cr, Ci, Sr, Si;
        upk2(C, Cr, Ci); upk2(S, Sr, Si);
        const float sc = 1.0f / 128.0f;
        float X1r = (Cr + Si) * sc, X1i = (Ci - Sr) * sc;
        float X2r = (Cr - Si) * sc, X2i = (Ci + Sr) * sc;

        // freq embed: c<384 uses position h (and 128-h), c>=384 uses w
        float al = alpha[c];
        int cb = (c < 384) ? c : (c - 384);
        float dv = expf((float)(cb & ~1) * (-9.210340371976184f / 384.0f));
        float p1, p2;
        if (c < 384) { p1 = (float)h; p2 = (float)(128 - h); }
        else         { p1 = p2 = (float)(wi + 2); }
        float e1, e2;
        if (c & 1) { e1 = cosf(p1 * dv); e2 = cosf(p2 * dv); }
        else       { e1 = sinf(p1 * dv); e2 = sinf(p2 * dv); }
        X1r += al * e1; X2r += al * e2;

        int m1 = hIdx * 15 + wi;            // h = hIdx+2
        int m2 = (29 - hIdx) * 15 + wi;     // h' = 128-h
        size_t base = ((size_t)b * 450) * 768 + c;
        g_X[base + (size_t)m1 * 768] = make_float2(X1r, X1i);
        g_X[base + (size_t)m2 * 768] = make_float2(X2r, X2i);
    }
}

// ===========================================================================
// Kernel 2: complex MLP per block k (96->96->96) + soft shrink. (unchanged)
// ===========================================================================
#define K2_SMEM 198656

__global__ __launch_bounds__(256) void k_mlp(
    const float* __restrict__ w1r, const float* __restrict__ b1r,
    const float* __restrict__ w1i, const float* __restrict__ b1i,
    const float* __restrict__ w2r, const float* __restrict__ b2r,
    const float* __restrict__ w2i, const float* __restrict__ b2i)
{
    extern __shared__ u64 smu[];
    u64* Xt  = smu;                      // 32*97
    u64* Mid = Xt + 32 * 97;             // 32*97
    float* sW1r = (float*)(Mid + 32 * 97);
    float* sW1i = sW1r + 9216;
    float* sW2r = sW1i + 9216;
    float* sW2i = sW2r + 9216;
    float* sb   = sW2i + 9216;           // b1r|b1i|b2r|b2i, 96 each

    const int t  = threadIdx.x;
    const int k  = blockIdx.y;
    const int r0 = blockIdx.x * 32;
    const int wo = k * 9216;

    for (int i = t; i < 9216; i += 256) {
        sW1r[i] = w1r[wo + i];
        sW1i[i] = w1i[wo + i];
        sW2r[i] = w2r[wo + i];
        sW2i[i] = w2i[wo + i];
    }
    if (t < 96) {
        sb[t]       = b1r[k * 96 + t];
        sb[96 + t]  = b1i[k * 96 + t];
        sb[192 + t] = b2r[k * 96 + t];
        sb[288 + t] = b2i[k * 96 + t];
    }
    for (int i = t; i < 32 * 96; i += 256) {
        int r = i / 96, ci = i - r * 96;
        int R = r0 + r; if (R > 3599) R = 3599;
        Xt[r * 97 + ci] = *(const u64*)&g_X[(size_t)R * 768 + k * 96 + ci];
    }
    __syncthreads();

    const int r  = t & 31;               // lane = row
    const int cg = t >> 5;               // warp = 12-col group
    const int c0 = cg * 12;
    u64 ar[6], ai[6];

    // ---- layer 1 ----
    #pragma unroll
    for (int p = 0; p < 6; p++) {
        int cc = c0 + 2 * p;
        float br0 = sb[cc], bi0 = sb[96 + cc];
        float br1 = sb[cc + 1], bi1 = sb[96 + cc + 1];
        ar[p] = pk2(br0 - bi0, br1 - bi1);
        ai[p] = pk2(br0 + bi0, br1 + bi1);
    }
    {
        const u64* xrow = Xt + r * 97;
        #pragma unroll 4
        for (int i = 0; i < 96; i++) {
            float xr, xi; upk2(xrow[i], xr, xi);
            u64 xrr = pk2(xr, xr), xii = pk2(xi, xi), xin = pk2(-xi, -xi);
            const float* wr  = sW1r + i * 96 + c0;
            const float* wii = sW1i + i * 96 + c0;
            #pragma unroll
            for (int p = 0; p < 6; p++) {
                u64 wr2 = *(const u64*)(wr + 2 * p);
                u64 wi2 = *(const u64*)(wii + 2 * p);
                ar[p] = f2fma(xrr, wr2, ar[p]);
                ar[p] = f2fma(xin, wi2, ar[p]);
                ai[p] = f2fma(xii, wr2, ai[p]);
                ai[p] = f2fma(xrr, wi2, ai[p]);
            }
        }
    }
    #pragma unroll
    for (int p = 0; p < 6; p++) {
        float r1a, r1b, i1a, i1b;
        upk2(ar[p], r1a, r1b); upk2(ai[p], i1a, i1b);
        Mid[r * 97 + c0 + 2 * p]     = pk2(r1a, i1a);
        Mid[r * 97 + c0 + 2 * p + 1] = pk2(r1b, i1b);
    }
    __syncthreads();

    // ---- layer 2 ----
    #pragma unroll
    for (int p = 0; p < 6; p++) {
        int cc = c0 + 2 * p;
        float br0 = sb[192 + cc], bi0 = sb[288 + cc];
        float br1 = sb[192 + cc + 1], bi1 = sb[288 + cc + 1];
        ar[p] = pk2(br0 - bi0, br1 - bi1);
        ai[p] = pk2(br0 + bi0, br1 + bi1);
    }
    {
        const u64* mrow = Mid + r * 97;
        #pragma unroll 4
        for (int i = 0; i < 96; i++) {
            float xr, xi; upk2(mrow[i], xr, xi);
            u64 xrr = pk2(xr, xr), xii = pk2(xi, xi), xin = pk2(-xi, -xi);
            const float* wr  = sW2r + i * 96 + c0;
            const float* wii = sW2i + i * 96 + c0;
            #pragma unroll
            for (int p = 0; p < 6; p++) {
                u64 wr2 = *(const u64*)(wr + 2 * p);
                u64 wi2 = *(const u64*)(wii + 2 * p);
                ar[p] = f2fma(xrr, wr2, ar[p]);
                ar[p] = f2fma(xin, wi2, ar[p]);
                ai[p] = f2fma(xii, wr2, ai[p]);
                ai[p] = f2fma(xrr, wi2, ai[p]);
            }
        }
    }
    int R = r0 + r;
    if (R < 3600) {
        float2* dst = g_F + (size_t)R * 768 + k * 96 + c0;
        #pragma unroll
        for (int p = 0; p < 6; p++) {
            float ra, rb, ia, ib;
            upk2(ar[p], ra, rb); upk2(ai[p], ia, ib);
            dst[2 * p]     = make_float2(shrinkf(ra), shrinkf(ia));
            dst[2 * p + 1] = make_float2(shrinkf(rb), shrinkf(ib));
        }
    }
}

// ===========================================================================
// Kernel 3: sparse inverse DFT with x- and y-folding.  One CTA per (b,c).
// smem (u64 units):
//   Fp [0 .. 450)          (Fr, Fi) per mode
//   cs4 [450 .. 706)       128 * ulonglong2 ((c,c),(s,s))
//   Pc [706 .. 2686)       30 hi * 66 x
//   Ps [2686 .. 4666)      30 hi * 66 x
//   Ua (f32) [4666 .. 5626)  15 hp * 128 x
//   Ub (f32) [5626 .. 6586)
// total 6586*8 = 52,688 B  -> 2 CTAs/SM (reg-limited)
// ===========================================================================
#define K3_SMEM 52688

__global__ __launch_bounds__(256, 2) void k_inv(float* __restrict__ out)
{
    extern __shared__ u64 smu[];
    u64* Fp = smu;                       // 450
    ulonglong2* cs4 = (ulonglong2*)(smu + 450);
    u64* Pc = smu + 706;                 // [hi*66 + x]
    u64* Ps = smu + 2686;
    float* Ua = (float*)(smu + 4666);    // [hp*128 + x]
    float* Ub = (float*)(smu + 5626);

    const int t  = threadIdx.x;
    const int bc = blockIdx.x;
    const int b  = bc / 768, c = bc - b * 768;

    if (t < 128) {
        float cv, sv;
        sincosf(t * PI2_128, &sv, &cv);
        ulonglong2 e; e.x = pk2(cv, cv); e.y = pk2(sv, sv);
        cs4[t] = e;
    }
    for (int i = t; i < 450; i += 256) {
        float2 f = g_F[((size_t)b * 450 + i) * 768 + c];
        Fp[i] = pk2(f.x, f.y);
    }
    __syncthreads();

    // ---- stage 1: Pc/Ps[hi][x] = Sum_w F * (cos, sin)((w+2) x), x=0..64 ----
    if (t < 240) {
        const int hi = t % 30, xg = t / 30;
        u64 F[15];
        #pragma unroll
        for (int w = 0; w < 15; w++) F[w] = Fp[hi * 15 + w];
        for (int k = 0; k < 9; k++) {
            int xx = xg + 8 * k;
            if (xx > 64) break;            // only xg==0 reaches k==8 (x=64)
            const int stp = (2 * xx) & 127;
            u64 cA = 0ull, sA = 0ull, cB = 0ull, sB = 0ull;
            int iA = stp;                  // w=0 -> 2x
            int iB = (3 * xx) & 127;       // w=1 -> 3x
            #pragma unroll
            for (int w = 0; w < 15; w += 2) {
                ulonglong2 tb = cs4[iA];
                cA = f2fma(F[w], tb.x, cA);
                sA = f2fma(F[w], tb.y, sA);
                iA = (iA + stp) & 127;
            }
            #pragma unroll
            for (int w = 1; w < 15; w += 2) {
                ulonglong2 tb = cs4[iB];
                cB = f2fma(F[w], tb.x, cB);
                sB = f2fma(F[w], tb.y, sB);
                iB = (iB + stp) & 127;
            }
            Pc[hi * 66 + xx] = f2add(cA, cB);
            Ps[hi * 66 + xx] = f2add(sA, sB);
        }
    }
    __syncthreads();

    // ---- combine: fold h-pairs + reconstruct x and 128-x ----
    // P[hi][x] = Pc + i Ps ; P[hi][128-x] = Pc - i Ps
    // Ua[hp][x] = P[hp][x].re + P[29-hp][x].re ; Ub = .im(hp) - .im(29-hp)
    for (int idx = t; idx < 15 * 65; idx += 256) {
        int hp = idx / 65, xx = idx - hp * 65;   // x = 0..64
        float c1r, c1i, s1r, s1i, c2r, c2i, s2r, s2i;
        upk2(Pc[hp * 66 + xx], c1r, c1i);
        upk2(Ps[hp * 66 + xx], s1r, s1i);
        upk2(Pc[(29 - hp) * 66 + xx], c2r, c2i);
        upk2(Ps[(29 - hp) * 66 + xx], s2r, s2i);
        // direct x
        float p1re = c1r - s1i, p1im = c1i + s1r;
        float p2re = c2r - s2i, p2im = c2i + s2r;
        Ua[hp * 128 + xx] = p1re + p2re;
        Ub[hp * 128 + xx] = p1im - p2im;
        // mirror 128-x (x=1..63)
        if (xx >= 1 && xx <= 63) {
            float m1re = c1r + s1i, m1im = c1i - s1r;
            float m2re = c2r + s2i, m2im = c2i - s2r;
            Ua[hp * 128 + 128 - xx] = m1re + m2re;
            Ub[hp * 128 + 128 - xx] = m1im - m2im;
        }
    }
    __syncthreads();

    // ---- stage 2 (folded y): Ce = Sum Ua cos(hy), Co = Sum Ub sin(hy) ----
    // out[y] = (Ce - Co)/64, out[128-y] = (Ce + Co)/64  (y = 0..63)
    {
        const int xg = t & 15, yg = t >> 4;   // 4 x-pairs, 4 y per thread
        const int y0 = yg * 4;
        u64 Ce[4][4], Co[4][4];
        #pragma unroll
        for (int jy = 0; jy < 4; jy++)
            #pragma unroll
            for (int p = 0; p < 4; p++) { Ce[jy][p] = 0ull; Co[jy][p] = 0ull; }

        for (int hp = 0; hp < 15; hp++) {
            u64 ua[4], ub[4];
            const float* uap = Ua + hp * 128 + 2 * xg;
            const float* ubp = Ub + hp * 128 + 2 * xg;
            #pragma unroll
            for (int p = 0; p < 4; p++) {
                ua[p] = *(const u64*)(uap + 32 * p);
                ub[p] = *(const u64*)(ubp + 32 * p);
            }
            const int h = hp + 2;
            #pragma unroll
            for (int jy = 0; jy < 4; jy++) {
                ulonglong2 tb = cs4[(h * (y0 + jy)) & 127];
                #pragma unroll
                for (int p = 0; p < 4; p++) {
                    Ce[jy][p] = f2fma(ua[p], tb.x, Ce[jy][p]);
                    Co[jy][p] = f2fma(ub[p], tb.y, Co[jy][p]);
                }
            }
        }
        float* outp = out + (size_t)bc * 16384 + 2 * xg;
        const float s = 1.0f / 64.0f;
        #pragma unroll
        for (int jy = 0; jy < 4; jy++) {
            int y = y0 + jy;
            float* rowA = outp + y * 128;
            float* rowB = outp + (128 - y) * 128;
            #pragma unroll
            for (int p = 0; p < 4; p++) {
                float er, ei, orr, oi;
                upk2(Ce[jy][p], er, ei);
                upk2(Co[jy][p], orr, oi);
                *(float2*)(rowA + 32 * p) = make_float2((er - orr) * s, (ei - oi) * s);
                if (y > 0)
                    *(float2*)(rowB + 32 * p) = make_float2((er + orr) * s, (ei + oi) * s);
            }
        }
    }

    // ---- y = 64 row: out[64][x] = (1/64) Sum_hp (-1)^hp Ua[hp][x] ----
    if (t < 64) {
        u64 acc = 0ull;
        #pragma unroll
        for (int hp = 0; hp < 15; hp++) {
            u64 ua = *(const u64*)(Ua + hp * 128 + 2 * t);
            float sg = (hp & 1) ? -1.0f : 1.0f;
            acc = f2fma(ua, pk2(sg, sg), acc);
        }
        float a, bv; upk2(acc, a, bv);
        const float s = 1.0f / 64.0f;
        *(float2*)(out + (size_t)bc * 16384 + 64 * 128 + 2 * t) =
            make_float2(a * s, bv * s);
    }
}

// ===========================================================================
extern "C" void kernel_launch(void* const* d_in, const int* in_sizes, int n_in,
                              void* d_out, int out_size)
{
    const float* x     = (const float*)d_in[0];
    const float* alpha = (const float*)d_in[1];
    const float* w1r   = (const float*)d_in[2];
    const float* b1r   = (const float*)d_in[3];
    const float* w1i   = (const float*)d_in[4];
    const float* b1i   = (const float*)d_in[5];
    const float* w2r   = (const float*)d_in[6];
    const float* b2r   = (const float*)d_in[7];
    const float* w2i   = (const float*)d_in[8];
    const float* b2i   = (const float*)d_in[9];
    float* out = (float*)d_out;

    cudaFuncSetAttribute(k_fwd, cudaFuncAttributeMaxDynamicSharedMemorySize, K1_SMEM);
    cudaFuncSetAttribute(k_mlp, cudaFuncAttributeMaxDynamicSharedMemorySize, K2_SMEM);
    cudaFuncSetAttribute(k_inv, cudaFuncAttributeMaxDynamicSharedMemorySize, K3_SMEM);

    k_fwd<<<6144, 256, K1_SMEM>>>(x, alpha);
    k_mlp<<<dim3(113, 8), 256, K2_SMEM>>>(w1r, b1r, w1i, b1i, w2r, b2r, w2i, b2i);
    k_inv<<<6144, 256, K3_SMEM>>>(out);
}